// round 15
// baseline (speedup 1.0000x reference)
#include <cuda_runtime.h>
#include <cstddef>

// ---------------------------------------------------------------------------
// SLAYER SRM-alpha SNN — R1-bit-identical arithmetic.
// R14 = R13 conv/dense + warp-staged scans: each warp stages 32 neurons x 32 t
// through a padded smem tile (coalesced LDG/STG, conflict-free LDS/STS,
// __syncwarp only). Dense combine folded into the final spike scan.
// Layout [N,C,H,W,T], T innermost, T=300, N=8.
// ---------------------------------------------------------------------------

#define T_LEN  300
#define TC4    75
#define NBATCH 8

typedef unsigned long long ull;

#define C_DS 0.90483741803595952f     // exp(-1/10)
#define C_B  0.27182818284590452f     // e/10
#define C_DR 0.36787944117144233f     // exp(-1)
#define C_A  (-54.365636569180902f)   // -2*10*e
#define C_TH 10.0f
#define C_POOL 11.0f

#define BUF_ELEMS 30105600
__device__ float g_bufA[BUF_ELEMS + 16];
__device__ float g_bufB[BUF_ELEMS + 16];

__device__ __forceinline__ ull ffma2(ull a, ull b, ull c) {
    ull d;
    asm("fma.rn.f32x2 %0, %1, %2, %3;" : "=l"(d) : "l"(a), "l"(b), "l"(c));
    return d;
}
__device__ __forceinline__ ull pack2(float lo, float hi) {
    return (ull)__float_as_uint(lo) | ((ull)__float_as_uint(hi) << 32);
}
__device__ __forceinline__ float lo32(ull v) { return __uint_as_float((unsigned)v); }
__device__ __forceinline__ float hi32(ull v) { return __uint_as_float((unsigned)(v >> 32)); }

#define ELT4(v, k) ((k) == 0 ? (v).x : (k) == 1 ? (v).y : (k) == 2 ? (v).z : (v).w)

// ---------------------------------------------------------------------------
// Warp-staged temporal scan. MODE: 0=psp, 1=spike+psp, 2=spike.
// 64 threads = 2 warps; each warp owns 32 neurons. Per 32-t tile:
//  A: coalesced LDG (4 rows x 8 quads per instr) -> stride-33 smem tile
//  B: each lane scans its own row (conflict-free scalar LDS/STS)
//  D: coalesced STG from tile.   Values bit-identical; order unchanged.
// ---------------------------------------------------------------------------
template<int MODE>
__global__ __launch_bounds__(64)
void scan_t(const float* __restrict__ x, float* __restrict__ y,
            int numNeurons) {
    __shared__ float tl[2][32][33];
    const int warp = threadIdx.x >> 5, lane = threadIdx.x & 31;
    const int n0 = blockIdx.x * 64 + warp * 32;
    const int rowA = lane >> 3;   // 0..3
    const int qA   = lane & 7;    // 0..7
    float (*T)[33] = tl[warp];
    float ps = 0.f, qs = 0.f, pr = 0.f, qr = 0.f;

    for (int tb = 0; tb < T_LEN; tb += 32) {
        const int CL = min(32, T_LEN - tb);
        #pragma unroll
        for (int r = 0; r < 8; r++) {
            int row = r * 4 + rowA;
            int gr  = n0 + row;
            float4 f = make_float4(0.f, 0.f, 0.f, 0.f);
            if (gr < numNeurons && qA * 4 < CL)
                f = *(const float4*)(x + (size_t)gr * T_LEN + tb + qA * 4);
            T[row][qA * 4 + 0] = f.x; T[row][qA * 4 + 1] = f.y;
            T[row][qA * 4 + 2] = f.z; T[row][qA * 4 + 3] = f.w;
        }
        __syncwarp();
        #pragma unroll 4
        for (int k = 0; k < CL; k++) {
            float u = T[lane][k];
            float outv;
            if (MODE == 0) {
                qs = C_DS * (qs + ps);
                ps = C_DS * ps + u;
                outv = C_B * qs;
            } else {
                qr = C_DR * (qr + pr);
                float vm = u + C_A * qr;
                float s = (vm >= C_TH) ? 1.0f : 0.0f;
                pr = C_DR * pr + s;
                if (MODE == 1) {
                    qs = C_DS * (qs + ps);
                    ps = C_DS * ps + s;
                    outv = C_B * qs;
                } else {
                    outv = s;
                }
            }
            T[lane][k] = outv;
        }
        __syncwarp();
        #pragma unroll
        for (int r = 0; r < 8; r++) {
            int row = r * 4 + rowA;
            int gr  = n0 + row;
            if (gr < numNeurons && qA * 4 < CL) {
                float4 f = make_float4(T[row][qA * 4 + 0], T[row][qA * 4 + 1],
                                       T[row][qA * 4 + 2], T[row][qA * 4 + 3]);
                *(float4*)(y + (size_t)gr * T_LEN + tb + qA * 4) = f;
            }
        }
        __syncwarp();
    }
}

// ---------------------------------------------------------------------------
// Warp-staged fused [spike+psp on 4 children] + 2x2 pool(*11) + [spike+psp].
// 64 threads = 2 warps; warp owns 32 pooled neurons (grids exact).
// Child rows staged per-child into stride-33 tiles; output reuses tile 0.
// Bit-identical to R1's scan+pool+scan chain.
// ---------------------------------------------------------------------------
__global__ __launch_bounds__(64)
void scanpool2x(const float* __restrict__ x, float* __restrict__ y,
                int C, int OH, int OW) {
    __shared__ float tl[2][4][32][33];
    __shared__ int   rbs[2][32][4];
    const int warp = threadIdx.x >> 5, lane = threadIdx.x & 31;
    const int n0 = blockIdx.x * 64 + warp * 32;
    const int gn = n0 + lane;
    {
        int ox = gn % OW; int r = gn / OW;
        int oy = r % OH;  r /= OH;
        int c  = r % C;   int n = r / C;
        const int W = OW * 2, H = OH * 2;
        int base = (((n * C + c) * H + 2 * oy) * W + 2 * ox) * T_LEN;
        rbs[warp][lane][0] = base;
        rbs[warp][lane][1] = base + T_LEN;
        rbs[warp][lane][2] = base + W * T_LEN;
        rbs[warp][lane][3] = base + (W + 1) * T_LEN;
    }
    __syncwarp();
    const int rowA = lane >> 3, qA = lane & 7;

    float cpr[4] = {0,0,0,0}, cqr[4] = {0,0,0,0};
    float cps[4] = {0,0,0,0}, cqs[4] = {0,0,0,0};
    float Ppr = 0.f, Pqr = 0.f, Pps = 0.f, Pqs = 0.f;

    for (int tb = 0; tb < T_LEN; tb += 32) {
        const int CL = min(32, T_LEN - tb);
        #pragma unroll
        for (int c = 0; c < 4; c++) {
            #pragma unroll
            for (int r = 0; r < 8; r++) {
                int row = r * 4 + rowA;
                float4 f = make_float4(0.f, 0.f, 0.f, 0.f);
                if (qA * 4 < CL)
                    f = *(const float4*)(x + rbs[warp][row][c] + tb + qA * 4);
                tl[warp][c][row][qA * 4 + 0] = f.x;
                tl[warp][c][row][qA * 4 + 1] = f.y;
                tl[warp][c][row][qA * 4 + 2] = f.z;
                tl[warp][c][row][qA * 4 + 3] = f.w;
            }
        }
        __syncwarp();
        #pragma unroll 4
        for (int k = 0; k < CL; k++) {
            float outc[4];
            #pragma unroll
            for (int c = 0; c < 4; c++) {
                float u = tl[warp][c][lane][k];
                cqr[c] = C_DR * (cqr[c] + cpr[c]);
                float vm = u + C_A * cqr[c];
                float s  = (vm >= C_TH) ? 1.0f : 0.0f;
                cpr[c] = C_DR * cpr[c] + s;
                cqs[c] = C_DS * (cqs[c] + cps[c]);
                cps[c] = C_DS * cps[c] + s;
                outc[c] = C_B * cqs[c];
            }
            float U = (outc[0] + outc[1] + outc[2] + outc[3]) * C_POOL;
            Pqr = C_DR * (Pqr + Ppr);
            float vm = U + C_A * Pqr;
            float s  = (vm >= C_TH) ? 1.0f : 0.0f;
            Ppr = C_DR * Ppr + s;
            Pqs = C_DS * (Pqs + Pps);
            Pps = C_DS * Pps + s;
            tl[warp][0][lane][k] = C_B * Pqs;
        }
        __syncwarp();
        #pragma unroll
        for (int r = 0; r < 8; r++) {
            int row = r * 4 + rowA;
            if (qA * 4 < CL) {
                float4 f = make_float4(tl[warp][0][row][qA * 4 + 0],
                                       tl[warp][0][row][qA * 4 + 1],
                                       tl[warp][0][row][qA * 4 + 2],
                                       tl[warp][0][row][qA * 4 + 3]);
                *(float4*)(y + (size_t)(n0 + row) * T_LEN + tb + qA * 4) = f;
            }
        }
        __syncwarp();
    }
}

// ---------------------------------------------------------------------------
// Direct conv (R13, unchanged): lane-permuted accumulators, CO_BLK=16 as 8
// f32x2 channel pairs, undup'd weights (4 LDS.128/tap), predicated zero-fill
// boundary loads. Accumulation order (ci,kh,kw) per output — R1-identical.
// ---------------------------------------------------------------------------
template<int CI, int CO, int CO_BLK, int K, int H, int W, int OH, int OW,
         int PAD, int UNR>
__global__ __launch_bounds__(256, 2)
void conv_kernel(const float* __restrict__ x, const float* __restrict__ wgt,
                 float* __restrict__ y) {
    constexpr int TAPS = CI * K * K;
    constexpr int NP = CO_BLK / 2;
    __shared__ float2 ws[TAPS * NP];
    const int oBase = blockIdx.y * CO_BLK;
    for (int i = threadIdx.x; i < TAPS * NP; i += blockDim.x) {
        int p = i % NP, tap = i / NP;
        ws[i] = make_float2(wgt[(oBase + 2 * p) * TAPS + tap],
                            wgt[(oBase + 2 * p + 1) * TAPS + tap]);
    }
    __syncthreads();

    long long g = (long long)blockIdx.x * blockDim.x + threadIdx.x;
    int tc = (int)(g % TC4); long long r = g / TC4;
    int ox = (int)(r % OW); r /= OW;
    int oy = (int)(r % OH); r /= OH;
    int n  = (int)r;
    if (n >= NBATCH) return;

    ull A[NP], B[NP], C[NP], D[NP];
    #pragma unroll
    for (int p = 0; p < NP; p++) { A[p] = 0; B[p] = 0; C[p] = 0; D[p] = 0; }

    const float* xb = x + (size_t)n * CI * H * W * T_LEN + tc * 4;

    #pragma unroll UNR
    for (int ci = 0; ci < CI; ci++) {
        #pragma unroll
        for (int kh = 0; kh < K; kh++) {
            const int iy = oy + kh - PAD;
            const bool vy = (unsigned)iy < (unsigned)H;
            const float* xrow = xb + (size_t)(ci * H + iy) * W * T_LEN;
            #pragma unroll
            for (int kw = 0; kw < K; kw++) {
                const int ix = ox + kw - PAD;
                const bool v = vy && ((unsigned)ix < (unsigned)W);
                float4 f = make_float4(0.f, 0.f, 0.f, 0.f);
                if (v) f = *(const float4*)(xrow + (size_t)ix * T_LEN);
                const ull x01 = ((const ull*)&f)[0];
                const ull x23 = ((const ull*)&f)[1];
                const ull x10 = pack2(f.y, f.x);
                const ull x32 = pack2(f.w, f.z);
                const float2* wrow = &ws[((ci * K + kh) * K + kw) * NP];
                #pragma unroll
                for (int p = 0; p < NP; p += 2) {
                    float4 wv = *(const float4*)(wrow + p);
                    ull w0 = ((ull*)&wv)[0];
                    ull w1 = ((ull*)&wv)[1];
                    A[p]   = ffma2(w0, x01, A[p]);
                    B[p]   = ffma2(w0, x10, B[p]);
                    C[p]   = ffma2(w0, x23, C[p]);
                    D[p]   = ffma2(w0, x32, D[p]);
                    A[p+1] = ffma2(w1, x01, A[p+1]);
                    B[p+1] = ffma2(w1, x10, B[p+1]);
                    C[p+1] = ffma2(w1, x23, C[p+1]);
                    D[p+1] = ffma2(w1, x32, D[p+1]);
                }
            }
        }
    }
    const size_t chstr = (size_t)OH * OW * T_LEN;
    size_t off0 = (((size_t)(n * CO + oBase) * OH + oy) * OW + ox) * T_LEN + tc * 4;
    #pragma unroll
    for (int p = 0; p < NP; p++) {
        *(float4*)(y + off0 + (size_t)(2 * p) * chstr) =
            make_float4(lo32(A[p]), lo32(B[p]), lo32(C[p]), lo32(D[p]));
        *(float4*)(y + off0 + (size_t)(2 * p + 1) * chstr) =
            make_float4(hi32(B[p]), hi32(A[p]), hi32(D[p]), hi32(C[p]));
    }
}

// ---------------------------------------------------------------------------
// Dense split-4 partials (internally sequential chunks of 784).
// ---------------------------------------------------------------------------
#define DOUT (NBATCH * 10 * T_LEN)     // 24000
#define DCHUNK 784                     // 3136 / 4

__global__ __launch_bounds__(256)
void dense_part(const float* __restrict__ x, const float* __restrict__ wgt,
                float* __restrict__ part) {
    int g = blockIdx.x * blockDim.x + threadIdx.x;
    if (g >= DOUT * 4) return;
    int c = g / DOUT;  int gg = g % DOUT;
    int t = gg % T_LEN; int r = gg / T_LEN;
    int o = r % 10;     int n = r / 10;
    const float* xb = x + (size_t)n * 3136 * T_LEN + (size_t)(c * DCHUNK) * T_LEN + t;
    const float* wb = wgt + o * 3136 + c * DCHUNK;
    float acc = 0.f;
    #pragma unroll 28
    for (int i = 0; i < DCHUNK; i++)
        acc = fmaf(wb[i], xb[(size_t)i * T_LEN], acc);
    part[g] = acc;
}

// ---------------------------------------------------------------------------
// Final: combine partials ((P0+P1)+P2)+P3 (same order as before) fused with
// the output spike scan. 80 neurons, one block.
// ---------------------------------------------------------------------------
__global__ __launch_bounds__(128)
void scan_out(const float* __restrict__ part, float* __restrict__ y) {
    int gn = threadIdx.x;
    if (gn >= 80) return;
    const float* p0 = part + (size_t)gn * T_LEN;
    const float* p1 = p0 + DOUT;
    const float* p2 = p1 + DOUT;
    const float* p3 = p2 + DOUT;
    float pr = 0.f, qr = 0.f;
    #pragma unroll 1
    for (int tb = 0; tb < T_LEN; tb += 4) {
        float4 a = *(const float4*)(p0 + tb);
        float4 b = *(const float4*)(p1 + tb);
        float4 c = *(const float4*)(p2 + tb);
        float4 d = *(const float4*)(p3 + tb);
        float o[4];
        #pragma unroll
        for (int k = 0; k < 4; k++) {
            float u = ((ELT4(a, k) + ELT4(b, k)) + ELT4(c, k)) + ELT4(d, k);
            qr = C_DR * (qr + pr);
            float vm = u + C_A * qr;
            float s = (vm >= C_TH) ? 1.0f : 0.0f;
            pr = C_DR * pr + s;
            o[k] = s;
        }
        *(float4*)(y + (size_t)gn * T_LEN + tb) = make_float4(o[0], o[1], o[2], o[3]);
    }
}

// ---------------------------------------------------------------------------

static inline int cdiv(long long a, long long b) { return (int)((a + b - 1) / b); }

extern "C" void kernel_launch(void* const* d_in, const int* in_sizes, int n_in,
                              void* d_out, int out_size) {
    const float* in = (const float*)d_in[0];   // [8,1,30,30,300]
    const float* w1 = (const float*)d_in[1];   // [16,1,5,5]
    const float* w2 = (const float*)d_in[2];   // [32,16,3,3]
    const float* w3 = (const float*)d_in[3];   // [64,32,3,3]
    const float* w4 = (const float*)d_in[4];   // [10,64,7,7]
    float* out = (float*)d_out;                // [8,10,300]

    float *bufA, *bufB;
    cudaGetSymbolAddress((void**)&bufA, g_bufA);
    cudaGetSymbolAddress((void**)&bufB, g_bufB);

    // P0 = psp(input)  [8,1,30,30,300]
    scan_t<0><<<cdiv(7200, 64), 64>>>(in, bufA, 7200);

    // u1 = conv1(P0)   [8,16,28,28,300]
    conv_kernel<1, 16, 16, 5, 30, 30, 28, 28, 1, 1>
        <<<dim3(cdiv((long long)NBATCH * 28 * 28 * TC4, 256), 1), 256>>>(bufA, w1, bufB);

    // Q2 = psp(spike(pool(psp(spike(u1)))))  [8,16,14,14,300]
    scanpool2x<<<25088 / 64, 64>>>(bufB, bufA, 16, 14, 14);

    // u3 = conv2(Q2)   [8,32,14,14,300]
    conv_kernel<16, 32, 16, 3, 14, 14, 14, 14, 1, 2>
        <<<dim3(cdiv((long long)NBATCH * 14 * 14 * TC4, 256), 2), 256>>>(bufA, w2, bufB);

    // Q4 = psp(spike(pool(psp(spike(u3)))))  [8,32,7,7,300]
    scanpool2x<<<12544 / 64, 64>>>(bufB, bufA, 32, 7, 7);

    // u5 = conv3(Q4)   [8,64,7,7,300]
    conv_kernel<32, 64, 16, 3, 7, 7, 7, 7, 1, 2>
        <<<dim3(cdiv((long long)NBATCH * 7 * 7 * TC4, 256), 4), 256>>>(bufA, w3, bufB);

    // Q5 = psp(spike(u5))  [8,64,7,7,300]
    scan_t<1><<<cdiv(25088, 64), 64>>>(bufB, bufA, 25088);

    // u6 partials, then fused combine + output spike scan
    float* part = bufB + 65536;
    dense_part<<<cdiv(DOUT * 4, 256), 256>>>(bufA, w4, part);
    scan_out<<<1, 128>>>(part, out);
}

// round 16
// speedup vs baseline: 1.7113x; 1.7113x over previous
#include <cuda_runtime.h>
#include <cstddef>

// ---------------------------------------------------------------------------
// SLAYER SRM-alpha SNN — R1-bit-identical arithmetic.
// R16 = R13 (best measured: smem-free scans, lane-permuted conv, dense split-4)
//     + scan_out fusion (R14, safe)
//     + scanpool via 4-lane groups: one child per lane, pooled drive assembled
//       with shfl_xor(1,2,3) so the writing lane's sum order is EXACTLY
//       ((o0+o1)+o2)+o3 — bit-identical; 4x thread parallelism.
// Layout [N,C,H,W,T], T innermost, T=300, N=8.
// ---------------------------------------------------------------------------

#define T_LEN  300
#define TC4    75
#define NBATCH 8

typedef unsigned long long ull;

#define C_DS 0.90483741803595952f     // exp(-1/10)
#define C_B  0.27182818284590452f     // e/10
#define C_DR 0.36787944117144233f     // exp(-1)
#define C_A  (-54.365636569180902f)   // -2*10*e
#define C_TH 10.0f
#define C_POOL 11.0f

#define BUF_ELEMS 30105600
__device__ float g_bufA[BUF_ELEMS + 16];
__device__ float g_bufB[BUF_ELEMS + 16];

__device__ __forceinline__ ull ffma2(ull a, ull b, ull c) {
    ull d;
    asm("fma.rn.f32x2 %0, %1, %2, %3;" : "=l"(d) : "l"(a), "l"(b), "l"(c));
    return d;
}
__device__ __forceinline__ ull pack2(float lo, float hi) {
    return (ull)__float_as_uint(lo) | ((ull)__float_as_uint(hi) << 32);
}
__device__ __forceinline__ float lo32(ull v) { return __uint_as_float((unsigned)v); }
__device__ __forceinline__ float hi32(ull v) { return __uint_as_float((unsigned)(v >> 32)); }

#define ELT(v, k) (((k) & 3) == 0 ? (v)[(k) >> 2].x : \
                   ((k) & 3) == 1 ? (v)[(k) >> 2].y : \
                   ((k) & 3) == 2 ? (v)[(k) >> 2].z : (v)[(k) >> 2].w)
#define ELT4(v, k) ((k) == 0 ? (v).x : (k) == 1 ? (v).y : (k) == 2 ? (v).z : (v).w)

// ---------------------------------------------------------------------------
// Temporal scan, smem-free (R13). MODE: 0=psp, 1=spike+psp, 2=spike.
// ---------------------------------------------------------------------------
template<int CL, int MODE>
__device__ __forceinline__ void scan_tile(const float* __restrict__ xr,
                                          float* __restrict__ yr,
                                          float& p_s, float& q_s,
                                          float& p_r, float& q_r) {
    constexpr int NQ = CL / 4;
    float4 v[NQ];
    #pragma unroll
    for (int q = 0; q < NQ; q++) v[q] = *(const float4*)(xr + q * 4);
    float o[CL];
    #pragma unroll
    for (int k = 0; k < CL; k++) {
        float u = ELT(v, k);
        if (MODE == 0) {
            q_s = C_DS * (q_s + p_s);
            p_s = C_DS * p_s + u;
            o[k] = C_B * q_s;
        } else {
            q_r = C_DR * (q_r + p_r);
            float vm = u + C_A * q_r;
            float s = (vm >= C_TH) ? 1.0f : 0.0f;
            p_r = C_DR * p_r + s;
            if (MODE == 1) {
                q_s = C_DS * (q_s + p_s);
                p_s = C_DS * p_s + s;
                o[k] = C_B * q_s;
            } else {
                o[k] = s;
            }
        }
    }
    #pragma unroll
    for (int q = 0; q < NQ; q++)
        *(float4*)(yr + q * 4) =
            make_float4(o[q * 4], o[q * 4 + 1], o[q * 4 + 2], o[q * 4 + 3]);
}

template<int MODE>
__global__ __launch_bounds__(128)
void scan_t(const float* __restrict__ x, float* __restrict__ y,
            int numNeurons) {
    int gn = blockIdx.x * 128 + threadIdx.x;
    if (gn >= numNeurons) return;
    const float* xr = x + (size_t)gn * T_LEN;
    float*       yr = y + (size_t)gn * T_LEN;
    float p_s = 0.f, q_s = 0.f, p_r = 0.f, q_r = 0.f;
    #pragma unroll 1
    for (int tb = 0; tb < 288; tb += 16)
        scan_tile<16, MODE>(xr + tb, yr + tb, p_s, q_s, p_r, q_r);
    scan_tile<12, MODE>(xr + 288, yr + 288, p_s, q_s, p_r, q_r);
}

// ---------------------------------------------------------------------------
// Lane-group scanpool: 4 consecutive lanes own one pooled neuron, one child
// each. Child spike+psp per lane (exact). Pooled drive assembled via
// shfl_xor(1,2,3); on the writing lane (ch==0) the order is
// (((o0+o1)+o2)+o3)*11 — bit-identical to reference. All lanes run the
// pooled recurrence; only lane ch==0 writes its (exact) outputs.
// Grid: numPooled*4 threads, exact multiples of 128.
// ---------------------------------------------------------------------------
template<int CL>
__device__ __forceinline__ void poolg_tile(const float* __restrict__ xc,
                                           float* __restrict__ yr, bool wlane,
                                           float& cp, float& cq,
                                           float& cps, float& cqs,
                                           float& Pp, float& Pq,
                                           float& Pps, float& Pqs) {
    constexpr int NQ = CL / 4;
    float4 v[NQ];
    #pragma unroll
    for (int q = 0; q < NQ; q++) v[q] = *(const float4*)(xc + q * 4);
    float o[CL];
    #pragma unroll
    for (int k = 0; k < CL; k++) {
        float u = ELT(v, k);
        // child spike + psp (exact per-child chain)
        cq = C_DR * (cq + cp);
        float vm = u + C_A * cq;
        float s  = (vm >= C_TH) ? 1.0f : 0.0f;
        cp = C_DR * cp + s;
        cqs = C_DS * (cqs + cps);
        cps = C_DS * cps + s;
        float oc = C_B * cqs;
        // pooled drive: on ch==0 lane operands arrive as o1,o2,o3
        float a = __shfl_xor_sync(0xffffffffu, oc, 1);
        float b = __shfl_xor_sync(0xffffffffu, oc, 2);
        float d = __shfl_xor_sync(0xffffffffu, oc, 3);
        float U = (((oc + a) + b) + d) * C_POOL;
        // pooled spike + psp (exact on ch==0; discarded elsewhere)
        Pq = C_DR * (Pq + Pp);
        float vm2 = U + C_A * Pq;
        float s2  = (vm2 >= C_TH) ? 1.0f : 0.0f;
        Pp = C_DR * Pp + s2;
        Pqs = C_DS * (Pqs + Pps);
        Pps = C_DS * Pps + s2;
        o[k] = C_B * Pqs;
    }
    if (wlane) {
        #pragma unroll
        for (int q = 0; q < NQ; q++)
            *(float4*)(yr + q * 4) =
                make_float4(o[q * 4], o[q * 4 + 1], o[q * 4 + 2], o[q * 4 + 3]);
    }
}

__global__ __launch_bounds__(128)
void scanpool2x(const float* __restrict__ x, float* __restrict__ y,
                int C, int OH, int OW) {
    const int gt = blockIdx.x * 128 + threadIdx.x;
    const int np = gt >> 2;        // pooled neuron
    const int ch = gt & 3;         // child index
    int ox = np % OW; int r = np / OW;
    int oy = r % OH;  r /= OH;
    int c  = r % C;   int n = r / C;
    const int W = OW * 2, H = OH * 2;
    size_t base = (((size_t)(n * C + c) * H + 2 * oy) * W + 2 * ox) * T_LEN;
    size_t coff = (ch == 0) ? 0 : (ch == 1) ? (size_t)T_LEN
                : (ch == 2) ? (size_t)W * T_LEN : (size_t)(W + 1) * T_LEN;
    const float* xc = x + base + coff;
    float* yr = y + (size_t)np * T_LEN;
    const bool wlane = (ch == 0);

    float cp = 0.f, cq = 0.f, cps = 0.f, cqs = 0.f;
    float Pp = 0.f, Pq = 0.f, Pps = 0.f, Pqs = 0.f;

    #pragma unroll 1
    for (int tb = 0; tb < 288; tb += 16)
        poolg_tile<16>(xc + tb, yr + tb, wlane, cp, cq, cps, cqs, Pp, Pq, Pps, Pqs);
    poolg_tile<12>(xc + 288, yr + 288, wlane, cp, cq, cps, cqs, Pp, Pq, Pps, Pqs);
}

// ---------------------------------------------------------------------------
// Direct conv (R13, unchanged): lane-permuted accumulators, CO_BLK=16 as 8
// f32x2 channel pairs, undup'd weights (4 LDS.128/tap), predicated zero-fill
// boundary loads. Accumulation order (ci,kh,kw) per output — R1-identical.
// ---------------------------------------------------------------------------
template<int CI, int CO, int CO_BLK, int K, int H, int W, int OH, int OW,
         int PAD, int UNR>
__global__ __launch_bounds__(256, 2)
void conv_kernel(const float* __restrict__ x, const float* __restrict__ wgt,
                 float* __restrict__ y) {
    constexpr int TAPS = CI * K * K;
    constexpr int NP = CO_BLK / 2;
    __shared__ float2 ws[TAPS * NP];
    const int oBase = blockIdx.y * CO_BLK;
    for (int i = threadIdx.x; i < TAPS * NP; i += blockDim.x) {
        int p = i % NP, tap = i / NP;
        ws[i] = make_float2(wgt[(oBase + 2 * p) * TAPS + tap],
                            wgt[(oBase + 2 * p + 1) * TAPS + tap]);
    }
    __syncthreads();

    long long g = (long long)blockIdx.x * blockDim.x + threadIdx.x;
    int tc = (int)(g % TC4); long long r = g / TC4;
    int ox = (int)(r % OW); r /= OW;
    int oy = (int)(r % OH); r /= OH;
    int n  = (int)r;
    if (n >= NBATCH) return;

    ull A[NP], B[NP], C[NP], D[NP];
    #pragma unroll
    for (int p = 0; p < NP; p++) { A[p] = 0; B[p] = 0; C[p] = 0; D[p] = 0; }

    const float* xb = x + (size_t)n * CI * H * W * T_LEN + tc * 4;

    #pragma unroll UNR
    for (int ci = 0; ci < CI; ci++) {
        #pragma unroll
        for (int kh = 0; kh < K; kh++) {
            const int iy = oy + kh - PAD;
            const bool vy = (unsigned)iy < (unsigned)H;
            const float* xrow = xb + (size_t)(ci * H + iy) * W * T_LEN;
            #pragma unroll
            for (int kw = 0; kw < K; kw++) {
                const int ix = ox + kw - PAD;
                const bool v = vy && ((unsigned)ix < (unsigned)W);
                float4 f = make_float4(0.f, 0.f, 0.f, 0.f);
                if (v) f = *(const float4*)(xrow + (size_t)ix * T_LEN);
                const ull x01 = ((const ull*)&f)[0];
                const ull x23 = ((const ull*)&f)[1];
                const ull x10 = pack2(f.y, f.x);
                const ull x32 = pack2(f.w, f.z);
                const float2* wrow = &ws[((ci * K + kh) * K + kw) * NP];
                #pragma unroll
                for (int p = 0; p < NP; p += 2) {
                    float4 wv = *(const float4*)(wrow + p);
                    ull w0 = ((ull*)&wv)[0];
                    ull w1 = ((ull*)&wv)[1];
                    A[p]   = ffma2(w0, x01, A[p]);
                    B[p]   = ffma2(w0, x10, B[p]);
                    C[p]   = ffma2(w0, x23, C[p]);
                    D[p]   = ffma2(w0, x32, D[p]);
                    A[p+1] = ffma2(w1, x01, A[p+1]);
                    B[p+1] = ffma2(w1, x10, B[p+1]);
                    C[p+1] = ffma2(w1, x23, C[p+1]);
                    D[p+1] = ffma2(w1, x32, D[p+1]);
                }
            }
        }
    }
    const size_t chstr = (size_t)OH * OW * T_LEN;
    size_t off0 = (((size_t)(n * CO + oBase) * OH + oy) * OW + ox) * T_LEN + tc * 4;
    #pragma unroll
    for (int p = 0; p < NP; p++) {
        *(float4*)(y + off0 + (size_t)(2 * p) * chstr) =
            make_float4(lo32(A[p]), lo32(B[p]), lo32(C[p]), lo32(D[p]));
        *(float4*)(y + off0 + (size_t)(2 * p + 1) * chstr) =
            make_float4(hi32(B[p]), hi32(A[p]), hi32(D[p]), hi32(C[p]));
    }
}

// ---------------------------------------------------------------------------
// Dense split-4 partials (internally sequential chunks of 784).
// ---------------------------------------------------------------------------
#define DOUT (NBATCH * 10 * T_LEN)     // 24000
#define DCHUNK 784                     // 3136 / 4

__global__ __launch_bounds__(256)
void dense_part(const float* __restrict__ x, const float* __restrict__ wgt,
                float* __restrict__ part) {
    int g = blockIdx.x * blockDim.x + threadIdx.x;
    if (g >= DOUT * 4) return;
    int c = g / DOUT;  int gg = g % DOUT;
    int t = gg % T_LEN; int r = gg / T_LEN;
    int o = r % 10;     int n = r / 10;
    const float* xb = x + (size_t)n * 3136 * T_LEN + (size_t)(c * DCHUNK) * T_LEN + t;
    const float* wb = wgt + o * 3136 + c * DCHUNK;
    float acc = 0.f;
    #pragma unroll 28
    for (int i = 0; i < DCHUNK; i++)
        acc = fmaf(wb[i], xb[(size_t)i * T_LEN], acc);
    part[g] = acc;
}

// ---------------------------------------------------------------------------
// Final: combine partials ((P0+P1)+P2)+P3 fused with the output spike scan.
// ---------------------------------------------------------------------------
__global__ __launch_bounds__(128)
void scan_out(const float* __restrict__ part, float* __restrict__ y) {
    int gn = threadIdx.x;
    if (gn >= 80) return;
    const float* p0 = part + (size_t)gn * T_LEN;
    const float* p1 = p0 + DOUT;
    const float* p2 = p1 + DOUT;
    const float* p3 = p2 + DOUT;
    float pr = 0.f, qr = 0.f;
    #pragma unroll 1
    for (int tb = 0; tb < T_LEN; tb += 4) {
        float4 a = *(const float4*)(p0 + tb);
        float4 b = *(const float4*)(p1 + tb);
        float4 c = *(const float4*)(p2 + tb);
        float4 d = *(const float4*)(p3 + tb);
        float o[4];
        #pragma unroll
        for (int k = 0; k < 4; k++) {
            float u = ((ELT4(a, k) + ELT4(b, k)) + ELT4(c, k)) + ELT4(d, k);
            qr = C_DR * (qr + pr);
            float vm = u + C_A * qr;
            float s = (vm >= C_TH) ? 1.0f : 0.0f;
            pr = C_DR * pr + s;
            o[k] = s;
        }
        *(float4*)(y + (size_t)gn * T_LEN + tb) = make_float4(o[0], o[1], o[2], o[3]);
    }
}

// ---------------------------------------------------------------------------

static inline int cdiv(long long a, long long b) { return (int)((a + b - 1) / b); }

extern "C" void kernel_launch(void* const* d_in, const int* in_sizes, int n_in,
                              void* d_out, int out_size) {
    const float* in = (const float*)d_in[0];   // [8,1,30,30,300]
    const float* w1 = (const float*)d_in[1];   // [16,1,5,5]
    const float* w2 = (const float*)d_in[2];   // [32,16,3,3]
    const float* w3 = (const float*)d_in[3];   // [64,32,3,3]
    const float* w4 = (const float*)d_in[4];   // [10,64,7,7]
    float* out = (float*)d_out;                // [8,10,300]

    float *bufA, *bufB;
    cudaGetSymbolAddress((void**)&bufA, g_bufA);
    cudaGetSymbolAddress((void**)&bufB, g_bufB);

    // P0 = psp(input)  [8,1,30,30,300]
    scan_t<0><<<cdiv(7200, 128), 128>>>(in, bufA, 7200);

    // u1 = conv1(P0)   [8,16,28,28,300]
    conv_kernel<1, 16, 16, 5, 30, 30, 28, 28, 1, 1>
        <<<dim3(cdiv((long long)NBATCH * 28 * 28 * TC4, 256), 1), 256>>>(bufA, w1, bufB);

    // Q2 = psp(spike(pool(psp(spike(u1)))))  [8,16,14,14,300]  (4 lanes/neuron)
    scanpool2x<<<25088 * 4 / 128, 128>>>(bufB, bufA, 16, 14, 14);

    // u3 = conv2(Q2)   [8,32,14,14,300]
    conv_kernel<16, 32, 16, 3, 14, 14, 14, 14, 1, 2>
        <<<dim3(cdiv((long long)NBATCH * 14 * 14 * TC4, 256), 2), 256>>>(bufA, w2, bufB);

    // Q4 = psp(spike(pool(psp(spike(u3)))))  [8,32,7,7,300]
    scanpool2x<<<12544 * 4 / 128, 128>>>(bufB, bufA, 32, 7, 7);

    // u5 = conv3(Q4)   [8,64,7,7,300]
    conv_kernel<32, 64, 16, 3, 7, 7, 7, 7, 1, 2>
        <<<dim3(cdiv((long long)NBATCH * 7 * 7 * TC4, 256), 4), 256>>>(bufA, w3, bufB);

    // Q5 = psp(spike(u5))  [8,64,7,7,300]
    scan_t<1><<<cdiv(25088, 128), 128>>>(bufB, bufA, 25088);

    // u6 partials, then fused combine + output spike scan
    float* part = bufB + 65536;
    dense_part<<<cdiv(DOUT * 4, 256), 256>>>(bufA, w4, part);
    scan_out<<<1, 128>>>(part, out);
}